// round 10
// baseline (speedup 1.0000x reference)
#include <cuda_runtime.h>
#include <math_constants.h>

// Hausdorff loss: x,y (8, 4096, 3) fp32 -> scalar, ONE kernel launch.
// |q-t|^2 = |q|^2 + (|t|^2 - 2 q.t); min/max on squared values, sqrt at end.
//
// f32x2 packed FMA: TWO QUERIES per fma.rn.f32x2 (4 independent chains of 3),
// targets stored DUPLICATED in smem ((x,x)(y,y)(z,z)(w,w)) so both packed
// halves come straight from two broadcast LDS.128 — no per-iter marshalling.
// FFMA2 rt=3 (RF banks) -> 2 FMA-lanes / 3 cyc = 1.33x scalar FFMA.
//
// Decomposition (148 SMs = 4 * 37): 2*8*37 = 592 CTAs = exactly 4/SM.
// Complement-bits atomicMax merge (identity 0 -> no init kernel); per-slab
// last-done CTA reduces + restores; global last-done emits the scalar.

#define NB 8
#define V  4096
#define TC 37                         // 2*8*37 = 592 CTAs = 148*4
#define THREADS 256
#define QPT 8                         // queries per thread per pass (4 chains)
#define NCH (QPT / 2)
#define NPASS (V / (QPT * THREADS))   // 2
#define TMAX 111                      // ceil(4096/37)
#define NSLAB (2 * NB)

struct __align__(16) TDup { float2 x, y, z, w; };   // duplicated target, 32B

__device__ unsigned g_comp[NSLAB * V];    // zero-init == identity for max(~bits)
__device__ unsigned g_max[NB];
__device__ unsigned g_slab_done[NSLAB];
__device__ unsigned g_done;

__device__ __forceinline__ unsigned long long pack2(float lo, float hi) {
    unsigned long long r;
    asm("mov.b64 %0, {%1, %2};" : "=l"(r) : "f"(lo), "f"(hi));
    return r;
}
__device__ __forceinline__ unsigned long long fma2(unsigned long long a,
                                                   unsigned long long b,
                                                   unsigned long long c) {
    unsigned long long d;
    asm("fma.rn.f32x2 %0, %1, %2, %3;" : "=l"(d) : "l"(a), "l"(b), "l"(c));
    return d;
}
__device__ __forceinline__ float2 unpack2(unsigned long long v) {
    float2 f;
    asm("mov.b64 {%0, %1}, %2;" : "=f"(f.x), "=f"(f.y) : "l"(v));
    return f;
}

__global__ void __launch_bounds__(THREADS, 4)
hd_main_kernel(const float* __restrict__ X, const float* __restrict__ Y,
               float* __restrict__ out) {
    __shared__ TDup sT[TMAX];
    __shared__ float wmax[THREADS / 32];
    __shared__ int s_role;

    const int tc  = blockIdx.x;
    const int b   = blockIdx.y;
    const int dir = blockIdx.z;
    const int slab_id = dir * NB + b;
    const float* __restrict__ Qp = (dir == 0 ? X : Y) + (size_t)b * V * 3;
    const float* __restrict__ Tp = (dir == 0 ? Y : X) + (size_t)b * V * 3;
    unsigned* __restrict__ slab = g_comp + (size_t)slab_id * V;

    const int t0 = (tc * V) / TC;
    const int nt = ((tc + 1) * V) / TC - t0;   // 110 or 111
    const int tid = threadIdx.x;

    // Stage duplicated targets: (x,x)(y,y)(z,z)(w,w), w = |t|^2.
    if (tid < nt) {
        const int g = t0 + tid;
        const float tx = Tp[g * 3 + 0];
        const float ty = Tp[g * 3 + 1];
        const float tz = Tp[g * 3 + 2];
        const float tw = tx * tx + ty * ty + tz * tz;
        sT[tid].x = make_float2(tx, tx);
        sT[tid].y = make_float2(ty, ty);
        sT[tid].z = make_float2(tz, tz);
        sT[tid].w = make_float2(tw, tw);
    }
    __syncthreads();

    #pragma unroll 1
    for (int p = 0; p < NPASS; p++) {
        const int qb = p * (QPT * THREADS) + tid;

        // Chain c packs queries (qb + 2c*THREADS, qb + (2c+1)*THREADS).
        unsigned long long ax2[NCH], ay2[NCH], az2[NCH];
        float m[QPT];
        #pragma unroll
        for (int c = 0; c < NCH; c++) {
            const int qa = qb + (2 * c) * THREADS;
            const int qc = qa + THREADS;
            ax2[c] = pack2(-2.0f * Qp[qa * 3 + 0], -2.0f * Qp[qc * 3 + 0]);
            ay2[c] = pack2(-2.0f * Qp[qa * 3 + 1], -2.0f * Qp[qc * 3 + 1]);
            az2[c] = pack2(-2.0f * Qp[qa * 3 + 2], -2.0f * Qp[qc * 3 + 2]);
            m[2 * c] = CUDART_INF_F;
            m[2 * c + 1] = CUDART_INF_F;
        }

        #pragma unroll 4
        for (int j = 0; j < nt; j++) {
            const ulonglong2* sp = reinterpret_cast<const ulonglong2*>(&sT[j]);
            const ulonglong2 xy = sp[0];   // broadcast LDS.128: (x,x)(y,y)
            const ulonglong2 zw = sp[1];   // broadcast LDS.128: (z,z)(w,w)
            #pragma unroll
            for (int c = 0; c < NCH; c++) {
                unsigned long long v = fma2(az2[c], zw.x, zw.y);
                v = fma2(ay2[c], xy.y, v);
                v = fma2(ax2[c], xy.x, v);
                const float2 f = unpack2(v);   // register-pair naming
                m[2 * c]     = fminf(m[2 * c],     f.x);
                m[2 * c + 1] = fminf(m[2 * c + 1], f.y);
            }
        }

        #pragma unroll
        for (int c = 0; c < NCH; c++) {
            const float2 fax = unpack2(ax2[c]);
            const float2 fay = unpack2(ay2[c]);
            const float2 faz = unpack2(az2[c]);
            // |q|^2 = 0.25 * (ax^2 + ay^2 + az^2)
            const float q2a = 0.25f * fmaf(fax.x, fax.x, fmaf(fay.x, fay.x, faz.x * faz.x));
            const float q2b = 0.25f * fmaf(fax.y, fax.y, fmaf(fay.y, fay.y, faz.y * faz.y));
            const float sa = fmaxf(q2a + m[2 * c], 0.0f);
            const float sb = fmaxf(q2b + m[2 * c + 1], 0.0f);
            atomicMax(&slab[qb + (2 * c) * THREADS],     ~__float_as_uint(sa));
            atomicMax(&slab[qb + (2 * c + 1) * THREADS], ~__float_as_uint(sb));
        }
    }

    // ---- per-slab last-done CTA reduces its slab ----
    __threadfence();
    __syncthreads();
    if (tid == 0)
        s_role = (atomicAdd(&g_slab_done[slab_id], 1u) == TC - 1);
    __syncthreads();
    if (!s_role) return;

    __threadfence();   // acquire

    float mm = 0.0f;
    {
        uint4* __restrict__ slab4 = reinterpret_cast<uint4*>(slab);
        #pragma unroll
        for (int i = tid; i < V / 4; i += THREADS) {
            const uint4 w = slab4[i];
            mm = fmaxf(mm, __uint_as_float(~w.x));
            mm = fmaxf(mm, __uint_as_float(~w.y));
            mm = fmaxf(mm, __uint_as_float(~w.z));
            mm = fmaxf(mm, __uint_as_float(~w.w));
            slab4[i] = make_uint4(0u, 0u, 0u, 0u);   // restore identity
        }
    }
    #pragma unroll
    for (int off = 16; off > 0; off >>= 1)
        mm = fmaxf(mm, __shfl_xor_sync(0xffffffffu, mm, off));
    if ((tid & 31) == 0) wmax[tid >> 5] = mm;
    __syncthreads();

    if (tid == 0) {
        float mx = wmax[0];
        #pragma unroll
        for (int w = 1; w < THREADS / 32; w++) mx = fmaxf(mx, wmax[w]);
        atomicMax(&g_max[b], __float_as_uint(mx));
        g_slab_done[slab_id] = 0u;

        __threadfence();
        if (atomicAdd(&g_done, 1u) == NSLAB - 1) {
            __threadfence();
            float s = 0.0f;
            #pragma unroll
            for (int i = 0; i < NB; i++) {
                s += sqrtf(__uint_as_float(g_max[i]));
                g_max[i] = 0u;
            }
            out[0] = s * (1.0f / (float)NB);   // LOSS_WEIGHT = 1.0
            g_done = 0u;
        }
    }
}

extern "C" void kernel_launch(void* const* d_in, const int* in_sizes, int n_in,
                              void* d_out, int out_size) {
    const float* x = (const float*)d_in[0];
    const float* y = (const float*)d_in[1];
    float* out = (float*)d_out;

    dim3 grid(TC, NB, 2);
    hd_main_kernel<<<grid, THREADS>>>(x, y, out);
}

// round 11
// speedup vs baseline: 1.0223x; 1.0223x over previous
#include <cuda_runtime.h>
#include <math_constants.h>

// Hausdorff loss: x,y (8, 4096, 3) fp32 -> scalar, ONE kernel launch.
// KEY: one distance matrix serves BOTH directions (row mins = x-side NN,
// column mins = y-side NN) -> half the FMA work of two separate passes.
// d^2 = |x|^2 + (|y|^2 - 2 x.y), clamped at 0 per pair (equivalent to
// clamping after the min, since min_j max(d,0) == max(min_j d, 0)).
//
// Decomposition: 8 batches x 74 target-chunks = 592 CTAs = 4/SM (148*4).
// CTA: stages its ~55 targets (x,y,z,|t|^2) in smem, scans all 4096 queries
// (8/thread, 2 passes).
//   row mins  -> register accumulators -> complement-bits atomicMax slab
//               (identity 0 => zero-init scratch, no init kernel)
//   col mins  -> per-thread FMNMX chain -> warp REDUX.MIN.U32 -> per-warp
//               smem cell; complete locally (CTA sees ALL queries).
// Per-slab last-done CTA (of 74) reduces+restores its slab; global last-done
// (of 8) emits the scalar and restores all state for graph replay.

#define NB 8
#define V  4096
#define TC 74                         // 8*74 = 592 CTAs = 148*4
#define THREADS 256
#define QPT 8
#define NPASS (V / (QPT * THREADS))   // 2
#define TMAX 56                       // ceil(4096/74)
#define NWARP (THREADS / 32)

__device__ unsigned g_comp[NB * V];   // zero-init == identity for max(~bits)
__device__ unsigned g_max[NB];
__device__ unsigned g_slab_done[NB];
__device__ unsigned g_done;

__global__ void __launch_bounds__(THREADS, 4)
hd_main_kernel(const float* __restrict__ X, const float* __restrict__ Y,
               float* __restrict__ out) {
    __shared__ float4 sT[TMAX];
    __shared__ unsigned scolw[TMAX][NWARP];  // per-warp col-min bits (nonneg)
    __shared__ float wmax[NWARP];
    __shared__ int s_role;

    const int tc = blockIdx.x;           // 0..73
    const int b  = blockIdx.y;
    const float* __restrict__ Xb = X + (size_t)b * V * 3;
    const float* __restrict__ Yb = Y + (size_t)b * V * 3;
    unsigned* __restrict__ slab = g_comp + (size_t)b * V;   // x-side NN^2

    const int t0 = (tc * V) / TC;
    const int nt = ((tc + 1) * V) / TC - t0;   // 55 or 56
    const int tid = threadIdx.x;
    const int wid = tid >> 5;
    const int lid = tid & 31;

    // Stage targets (y-points): (x, y, z, |t|^2).
    if (tid < nt) {
        const int g = t0 + tid;
        const float tx = Yb[g * 3 + 0];
        const float ty = Yb[g * 3 + 1];
        const float tz = Yb[g * 3 + 2];
        sT[tid] = make_float4(tx, ty, tz, tx * tx + ty * ty + tz * tz);
    }
    for (int i = tid; i < TMAX * NWARP; i += THREADS)
        (&scolw[0][0])[i] = 0x7F800000u;     // +inf
    __syncthreads();

    #pragma unroll 1
    for (int p = 0; p < NPASS; p++) {
        const int qb = p * (QPT * THREADS) + tid;

        float ax[QPT], ay[QPT], az[QPT], x2[QPT], m[QPT];
        #pragma unroll
        for (int k = 0; k < QPT; k++) {
            const int q = qb + k * THREADS;
            const float qx = Xb[q * 3 + 0];
            const float qy = Xb[q * 3 + 1];
            const float qz = Xb[q * 3 + 2];
            ax[k] = -2.0f * qx; ay[k] = -2.0f * qy; az[k] = -2.0f * qz;
            x2[k] = qx * qx + qy * qy + qz * qz;
            m[k]  = CUDART_INF_F;
        }

        #pragma unroll 4
        for (int j = 0; j < nt; j++) {
            const float4 t = sT[j];          // broadcast LDS.128
            float cm = CUDART_INF_F;         // col min over this thread's 8
            #pragma unroll
            for (int k = 0; k < QPT; k++) {
                const float v  = fmaf(ax[k], t.x,
                                 fmaf(ay[k], t.y,
                                 fmaf(az[k], t.z, t.w)));
                const float d2 = fmaxf(v + x2[k], 0.0f);   // clamped d^2
                m[k] = fminf(m[k], d2);      // row (x-side)
                cm   = fminf(cm, d2);        // col (y-side)
            }
            // Warp-wide col min (nonneg floats: uint order == float order).
            const unsigned r = __reduce_min_sync(0xffffffffu,
                                                 __float_as_uint(cm));
            if (lid == 0)
                scolw[j][wid] = min(scolw[j][wid], r);   // warp-private cell
        }

        #pragma unroll
        for (int k = 0; k < QPT; k++)
            atomicMax(&slab[qb + k * THREADS], ~__float_as_uint(m[k]));
    }

    // ---- y-side: column results are COMPLETE in this CTA ----
    __syncthreads();
    float my = 0.0f;
    if (tid < nt) {
        unsigned u = scolw[tid][0];
        #pragma unroll
        for (int w = 1; w < NWARP; w++) u = min(u, scolw[tid][w]);
        my = __uint_as_float(u);             // NN^2 for target t0+tid
    }
    #pragma unroll
    for (int off = 16; off > 0; off >>= 1)
        my = fmaxf(my, __shfl_xor_sync(0xffffffffu, my, off));
    if (lid == 0) wmax[wid] = my;
    __syncthreads();
    if (tid == 0) {
        float mx = wmax[0];
        #pragma unroll
        for (int w = 1; w < NWARP; w++) mx = fmaxf(mx, wmax[w]);
        atomicMax(&g_max[b], __float_as_uint(mx));
    }

    // ---- per-slab last-done CTA reduces the x-side slab ----
    __threadfence();
    __syncthreads();
    if (tid == 0)
        s_role = (atomicAdd(&g_slab_done[b], 1u) == TC - 1);
    __syncthreads();
    if (!s_role) return;

    __threadfence();   // acquire: all 74 CTAs' atomics visible

    float mm = 0.0f;
    {
        uint4* __restrict__ slab4 = reinterpret_cast<uint4*>(slab);
        #pragma unroll
        for (int i = tid; i < V / 4; i += THREADS) {
            const uint4 w = slab4[i];
            mm = fmaxf(mm, __uint_as_float(~w.x));
            mm = fmaxf(mm, __uint_as_float(~w.y));
            mm = fmaxf(mm, __uint_as_float(~w.z));
            mm = fmaxf(mm, __uint_as_float(~w.w));
            slab4[i] = make_uint4(0u, 0u, 0u, 0u);   // restore identity
        }
    }
    #pragma unroll
    for (int off = 16; off > 0; off >>= 1)
        mm = fmaxf(mm, __shfl_xor_sync(0xffffffffu, mm, off));
    if (lid == 0) wmax[wid] = mm;
    __syncthreads();

    if (tid == 0) {
        float mx = wmax[0];
        #pragma unroll
        for (int w = 1; w < NWARP; w++) mx = fmaxf(mx, wmax[w]);
        atomicMax(&g_max[b], __float_as_uint(mx));
        g_slab_done[b] = 0u;                 // restore

        __threadfence();
        if (atomicAdd(&g_done, 1u) == NB - 1) {   // global last: finalize
            __threadfence();
            float s = 0.0f;
            #pragma unroll
            for (int i = 0; i < NB; i++) {
                s += sqrtf(__uint_as_float(g_max[i]));
                g_max[i] = 0u;               // restore
            }
            out[0] = s * (1.0f / (float)NB); // LOSS_WEIGHT = 1.0
            g_done = 0u;                     // restore
        }
    }
}

extern "C" void kernel_launch(void* const* d_in, const int* in_sizes, int n_in,
                              void* d_out, int out_size) {
    const float* x = (const float*)d_in[0];
    const float* y = (const float*)d_in[1];
    float* out = (float*)d_out;

    dim3 grid(TC, NB);
    hd_main_kernel<<<grid, THREADS>>>(x, y, out);
}

// round 12
// speedup vs baseline: 1.0576x; 1.0346x over previous
#include <cuda_runtime.h>
#include <math_constants.h>

// Hausdorff loss: x,y (8, 4096, 3) fp32 -> scalar, ONE kernel launch.
// |q-t|^2 = |q|^2 + (|t|^2 - 2 q.t); min/max on squared values, sqrt at end.
//
// Proven-best composition:
//   main loop  = R8's QPT=4 scan (measured ~39.7us, ~94% issue):
//                work unit (dir, b, target-chunk), 2*8*37 = 592 CTAs = 4/SM,
//                each CTA scans all 4096 queries (4/thread, 4 passes) against
//                its ~111-target smem chunk. 17-slot inner body, no REDUX.
//   tail       = R9's fused per-slab reduce (replaces the 10us reduce launch):
//                last-done-of-37 CTA reduces its own slab (uint4, parallel
//                across slabs, overlapped with stragglers), restores zeros;
//                global last-done emits the scalar and resets all state.
// Complement-bits merge: for s >= 0, min(bits) == ~max(~bits), identity 0
// ==> zero-initialized __device__ scratch, no init kernel, replay-safe.

#define NB 8
#define V  4096
#define TC 37                         // 2*8*37 = 592 CTAs = 148*4
#define THREADS 256
#define QPT 4                         // queries per thread per pass
#define NPASS (V / (QPT * THREADS))   // 4
#define TMAX 111                      // ceil(4096/37)
#define NSLAB (2 * NB)                // 16
#define NWARP (THREADS / 32)

__device__ unsigned g_comp[NSLAB * V];    // zero-init == identity for max(~bits)
__device__ unsigned g_max[NB];
__device__ unsigned g_slab_done[NSLAB];
__device__ unsigned g_done;

__global__ void __launch_bounds__(THREADS, 4)
hd_main_kernel(const float* __restrict__ X, const float* __restrict__ Y,
               float* __restrict__ out) {
    __shared__ float4 sT[TMAX];
    __shared__ float wmax[NWARP];
    __shared__ int s_role;

    const int tc  = blockIdx.x;          // 0..36
    const int b   = blockIdx.y;
    const int dir = blockIdx.z;
    const int slab_id = dir * NB + b;
    const float* __restrict__ Qp = (dir == 0 ? X : Y) + (size_t)b * V * 3;
    const float* __restrict__ Tp = (dir == 0 ? Y : X) + (size_t)b * V * 3;
    unsigned* __restrict__ slab = g_comp + (size_t)slab_id * V;

    const int t0 = (tc * V) / TC;
    const int nt = ((tc + 1) * V) / TC - t0;   // 110 or 111
    const int tid = threadIdx.x;
    const int wid = tid >> 5;
    const int lid = tid & 31;

    // Stage this chunk's targets: (x, y, z, |t|^2).
    if (tid < nt) {
        const int g = t0 + tid;
        const float tx = Tp[g * 3 + 0];
        const float ty = Tp[g * 3 + 1];
        const float tz = Tp[g * 3 + 2];
        sT[tid] = make_float4(tx, ty, tz, tx * tx + ty * ty + tz * tz);
    }
    __syncthreads();

    #pragma unroll 1
    for (int p = 0; p < NPASS; p++) {
        const int qb = p * (QPT * THREADS) + tid;

        float ax[QPT], ay[QPT], az[QPT], q2[QPT], m[QPT];
        #pragma unroll
        for (int k = 0; k < QPT; k++) {
            const int q = qb + k * THREADS;
            const float qx = Qp[q * 3 + 0];
            const float qy = Qp[q * 3 + 1];
            const float qz = Qp[q * 3 + 2];
            ax[k] = -2.0f * qx; ay[k] = -2.0f * qy; az[k] = -2.0f * qz;
            q2[k] = qx * qx + qy * qy + qz * qz;
            m[k]  = CUDART_INF_F;
        }

        #pragma unroll 4
        for (int j = 0; j < nt; j++) {
            const float4 t = sT[j];   // broadcast LDS.128
            #pragma unroll
            for (int k = 0; k < QPT; k++) {
                const float v = fmaf(ax[k], t.x,
                                fmaf(ay[k], t.y,
                                fmaf(az[k], t.z, t.w)));
                m[k] = fminf(m[k], v);
            }
        }

        #pragma unroll
        for (int k = 0; k < QPT; k++) {
            const float s = fmaxf(q2[k] + m[k], 0.0f);
            // min over chunks == ~(max over chunks of ~bits); identity 0.
            atomicMax(&slab[qb + k * THREADS], ~__float_as_uint(s));
        }
    }

    // ---- per-slab last-done CTA reduces its slab (parallel, overlapped) ----
    __threadfence();
    __syncthreads();
    if (tid == 0)
        s_role = (atomicAdd(&g_slab_done[slab_id], 1u) == TC - 1);
    __syncthreads();
    if (!s_role) return;

    __threadfence();   // acquire: all 37 chunk CTAs' atomics visible

    float mm = 0.0f;
    {   // 4096 words, 256 threads, uint4-vectorized.
        uint4* __restrict__ slab4 = reinterpret_cast<uint4*>(slab);
        #pragma unroll
        for (int i = tid; i < V / 4; i += THREADS) {
            const uint4 w = slab4[i];
            mm = fmaxf(mm, __uint_as_float(~w.x));
            mm = fmaxf(mm, __uint_as_float(~w.y));
            mm = fmaxf(mm, __uint_as_float(~w.z));
            mm = fmaxf(mm, __uint_as_float(~w.w));
            slab4[i] = make_uint4(0u, 0u, 0u, 0u);   // restore identity
        }
    }
    #pragma unroll
    for (int off = 16; off > 0; off >>= 1)
        mm = fmaxf(mm, __shfl_xor_sync(0xffffffffu, mm, off));
    if (lid == 0) wmax[wid] = mm;
    __syncthreads();

    if (tid == 0) {
        float mx = wmax[0];
        #pragma unroll
        for (int w = 1; w < NWARP; w++) mx = fmaxf(mx, wmax[w]);
        atomicMax(&g_max[b], __float_as_uint(mx));   // nonneg bits
        g_slab_done[slab_id] = 0u;                   // restore (all 37 arrived)

        __threadfence();
        if (atomicAdd(&g_done, 1u) == NSLAB - 1) {   // global last: finalize
            __threadfence();
            float s = 0.0f;
            #pragma unroll
            for (int i = 0; i < NB; i++) {
                s += sqrtf(__uint_as_float(g_max[i]));
                g_max[i] = 0u;                       // restore
            }
            out[0] = s * (1.0f / (float)NB);         // LOSS_WEIGHT = 1.0
            g_done = 0u;                             // restore
        }
    }
}

extern "C" void kernel_launch(void* const* d_in, const int* in_sizes, int n_in,
                              void* d_out, int out_size) {
    const float* x = (const float*)d_in[0];
    const float* y = (const float*)d_in[1];
    float* out = (float*)d_out;

    dim3 grid(TC, NB, 2);
    hd_main_kernel<<<grid, THREADS>>>(x, y, out);
}